// round 5
// baseline (speedup 1.0000x reference)
#include <cuda_runtime.h>
#include <math.h>

// Problem dims (fixed by metadata): E = B*N*K = 32768
#define E_MAX 32768

// Scratch (device globals: allocation-free per harness rules)
// g_h is stored TRANSPOSED: [c][e] so kernel2 can cp.async contiguous 32-edge rows
__device__ float g_h[64 * E_MAX];
__device__ float g_tmp[E_MAX * 288];  // feats@basis, [e][j=i*3+f][m]

__device__ __forceinline__ float gelu_exact(float v) {
    return 0.5f * v * (1.0f + erff(v * 0.70710678118654752440f));
}

// ---- f32x2 packed-FMA helpers (sm_103a FFMA2) -----------------------------
typedef unsigned long long ull;

__device__ __forceinline__ ull dup2(float v) {
    union { float2 f2; ull u; } c;
    c.f2 = make_float2(v, v);
    return c.u;
}
#define FMA2(acc, a, b) \
    asm("fma.rn.f32x2 %0, %1, %2, %0;" : "+l"(acc) : "l"(a), "l"(b))

// ---- cp.async helpers -----------------------------------------------------
__device__ __forceinline__ void cp16(void* sdst, const void* gsrc) {
    unsigned s = (unsigned)__cvta_generic_to_shared(sdst);
    asm volatile("cp.async.cg.shared.global [%0], [%1], 16;" :: "r"(s), "l"(gsrc));
}
__device__ __forceinline__ void cp_commit() {
    asm volatile("cp.async.commit_group;");
}
template <int N>
__device__ __forceinline__ void cp_wait() {
    asm volatile("cp.async.wait_group %0;" :: "n"(N));
}

// ---------------------------------------------------------------------------
// Kernel 1: one warp per edge. MLP (Linear->LN->GELU)x2  +  tmp = feats@basis
// ---------------------------------------------------------------------------
__global__ __launch_bounds__(256)
void mlp_tmp_kernel(const float* __restrict__ edges,
                    const float* __restrict__ feats,
                    const float* __restrict__ basis,
                    const float* __restrict__ W1, const float* __restrict__ b1,
                    const float* __restrict__ g1, const float* __restrict__ beta1,
                    const float* __restrict__ W2, const float* __restrict__ b2,
                    const float* __restrict__ g2, const float* __restrict__ beta2,
                    int E)
{
    __shared__ float W1s[32 * 64];
    __shared__ float W2s[64 * 64];
    int tid = threadIdx.x;
    for (int i = tid; i < 32 * 64; i += blockDim.x) W1s[i] = W1[i];
    for (int i = tid; i < 64 * 64; i += blockDim.x) W2s[i] = W2[i];
    __syncthreads();

    int warp = tid >> 5, lane = tid & 31;
    int e = blockIdx.x * 8 + warp;
    if (e >= E) return;

    const unsigned FULL = 0xffffffffu;

    float xv = edges[(size_t)e * 32 + lane];
    float t0 = b1[lane], t1 = b1[lane + 32];
    #pragma unroll
    for (int k = 0; k < 32; k++) {
        float xk = __shfl_sync(FULL, xv, k);
        t0 = fmaf(xk, W1s[k * 64 + lane], t0);
        t1 = fmaf(xk, W1s[k * 64 + lane + 32], t1);
    }
    float s = t0 + t1, sq = t0 * t0 + t1 * t1;
    #pragma unroll
    for (int o = 16; o > 0; o >>= 1) {
        s  += __shfl_xor_sync(FULL, s, o);
        sq += __shfl_xor_sync(FULL, sq, o);
    }
    float mean = s * (1.0f / 64.0f);
    float var  = sq * (1.0f / 64.0f) - mean * mean;
    float rstd = rsqrtf(var + 1e-5f);
    float h0 = gelu_exact((t0 - mean) * rstd * g1[lane]      + beta1[lane]);
    float h1 = gelu_exact((t1 - mean) * rstd * g1[lane + 32] + beta1[lane + 32]);

    t0 = b2[lane]; t1 = b2[lane + 32];
    #pragma unroll
    for (int k = 0; k < 32; k++) {
        float a = __shfl_sync(FULL, h0, k);
        float b = __shfl_sync(FULL, h1, k);
        t0 = fmaf(a, W2s[k * 64 + lane],             t0);
        t0 = fmaf(b, W2s[(k + 32) * 64 + lane],      t0);
        t1 = fmaf(a, W2s[k * 64 + lane + 32],        t1);
        t1 = fmaf(b, W2s[(k + 32) * 64 + lane + 32], t1);
    }
    s = t0 + t1; sq = t0 * t0 + t1 * t1;
    #pragma unroll
    for (int o = 16; o > 0; o >>= 1) {
        s  += __shfl_xor_sync(FULL, s, o);
        sq += __shfl_xor_sync(FULL, sq, o);
    }
    mean = s * (1.0f / 64.0f);
    var  = sq * (1.0f / 64.0f) - mean * mean;
    rstd = rsqrtf(var + 1e-5f);
    float o0 = gelu_exact((t0 - mean) * rstd * g2[lane]      + beta2[lane]);
    float o1 = gelu_exact((t1 - mean) * rstd * g2[lane + 32] + beta2[lane + 32]);
    // transposed store: g_h[c][e]
    g_h[(size_t)lane * E_MAX + e]        = o0;
    g_h[(size_t)(lane + 32) * E_MAX + e] = o1;

    // tmp[e][i*3+f][m] = sum_k feats[e,i,k] * basis[e,k,f*3+m]
    const float* fp = feats + (size_t)e * 96 + lane * 3;
    float f0 = fp[0], f1 = fp[1], f2 = fp[2];
    const float* bp = basis + (size_t)e * 27;
    #pragma unroll
    for (int q = 0; q < 9; q++) {
        float v = f0 * bp[q] + f1 * bp[9 + q] + f2 * bp[18 + q];
        g_tmp[(size_t)e * 288 + lane * 9 + q] = v;
    }
}

// ---------------------------------------------------------------------------
// Kernel 2: persistent slab CTAs.
// CTA = 1 slab of 384 W3 columns (4 output channels), loops over 32-edge tiles.
// 384 threads: GEMM thread-tile = 4 edges x 8 cols (split {4cg, 192+4cg}),
// f32x2 packed FMA along column pairs.
// ---------------------------------------------------------------------------
#define ETILE 32
#define K2_THREADS 384
#define NE_CTAS 18
// smem float offsets
#define WS_OFF    0            // [64][384]
#define HS_OFF    24576        // [2][64][32] double-buffered
#define TMPS_OFF  28672        // [32][292]
#define RWS_OFF   38016        // [32][388]
#define SM2_FLOATS 50432       // 201,728 bytes
#define TMPS_STRIDE 292
#define RWS_STRIDE  388

__global__ __launch_bounds__(K2_THREADS, 1)
void fused_rw_kernel(const float* __restrict__ W3, float* __restrict__ out, int E)
{
    extern __shared__ float sm2[];
    float* Ws   = sm2 + WS_OFF;
    float* hsA  = sm2 + HS_OFF;          // two buffers of 2048 floats
    float* tmps = sm2 + TMPS_OFF;
    float* rws  = sm2 + RWS_OFF;

    const int tid = threadIdx.x;
    const int slab = blockIdx.y;          // 0..7, covers cols slab*384..+383
    const int colbase = slab * 384;
    const int tiles = (E + ETILE - 1) / ETILE;

    // GEMM mapping
    const int cg  = tid % 48;             // cols {4cg..4cg+3} and {192+4cg..}
    const int eg  = tid / 48;             // edges eg*4..eg*4+3
    const int cg4 = cg * 4;
    const int e4  = eg * 4;
    // contraction mapping
    const int m  = tid % 3;
    const int p  = tid / 3;
    const int el = p & 31;
    const int oo = p >> 5;                // 0..3

    // ---- prologue: async-load W slab + first h tile ----
    for (int q = tid; q < 64 * 96; q += K2_THREADS) {
        int c = q / 96, v = (q - c * 96) * 4;
        cp16(Ws + c * 384 + v, W3 + (size_t)c * 3072 + colbase + v);
    }
    {
        int t0 = blockIdx.x;
        if (t0 < tiles) {
            int e0 = t0 * ETILE;
            for (int q = tid; q < 64 * 8; q += K2_THREADS) {
                int c = q >> 3, v = (q & 7) * 4;
                cp16(hsA + c * 32 + v, g_h + (size_t)c * E_MAX + e0 + v);
            }
        }
    }
    cp_commit();

    bool first = true;
    int par = 0;

    for (int tt = blockIdx.x; tt < tiles; tt += NE_CTAS) {
        int e0 = tt * ETILE;

        if (first) {
            cp_wait<0>();
            __syncthreads();
            first = false;
        }

        // ---- issue tmps(tt) : group T ----
        for (int q = tid; q < 32 * 72; q += K2_THREADS) {
            int r = q / 72, v = (q - r * 72) * 4;
            cp16(tmps + r * TMPS_STRIDE + v, g_tmp + (size_t)(e0 + r) * 288 + v);
        }
        cp_commit();

        // ---- issue hs(tt + NE) into other buffer : group H ----
        {
            int tn = tt + NE_CTAS;
            if (tn < tiles) {
                int en = tn * ETILE;
                float* hd = hsA + ((par ^ 1) << 11);
                for (int q = tid; q < 64 * 8; q += K2_THREADS) {
                    int c = q >> 3, v = (q & 7) * 4;
                    cp16(hd + c * 32 + v, g_h + (size_t)c * E_MAX + en + v);
                }
            }
            cp_commit();   // commit even if empty to keep group accounting
        }

        // ---- GEMM: rw[32e][384c] = h[32][64] @ Ws[64][384], f32x2 packed ----
        const float* hsb = hsA + (par << 11);
        ull acc[4][4];
        #pragma unroll
        for (int i = 0; i < 4; i++)
            #pragma unroll
            for (int j = 0; j < 4; j++) acc[i][j] = 0ull;

        #pragma unroll 8
        for (int c = 0; c < 64; c++) {
            ulonglong2 wa = *(const ulonglong2*)(Ws + c * 384 + cg4);
            ulonglong2 wb = *(const ulonglong2*)(Ws + c * 384 + 192 + cg4);
            ull h2[4];
            #pragma unroll
            for (int i = 0; i < 4; i++) h2[i] = dup2(hsb[c * 32 + e4 + i]);
            #pragma unroll
            for (int i = 0; i < 4; i++) {
                FMA2(acc[i][0], h2[i], wa.x);
                FMA2(acc[i][1], h2[i], wa.y);
                FMA2(acc[i][2], h2[i], wb.x);
                FMA2(acc[i][3], h2[i], wb.y);
            }
        }

        cp_wait<1>();   // tmps(tt) landed (H may still be in flight)

        #pragma unroll
        for (int i = 0; i < 4; i++) {
            float* row = rws + (e4 + i) * RWS_STRIDE;
            *(ulonglong2*)(row + cg4)       = make_ulonglong2(acc[i][0], acc[i][1]);
            *(ulonglong2*)(row + 192 + cg4) = make_ulonglong2(acc[i][2], acc[i][3]);
        }
        __syncthreads();   // rws + tmps visible to all

        // ---- contraction: out[e,o,m] = sum_j rw[e][oo*96+j] * tmp[e][j][m] ----
        {
            const float* rp = rws  + el * RWS_STRIDE  + oo * 96;
            const float* tp = tmps + el * TMPS_STRIDE + m;
            float a = 0.0f;
            #pragma unroll
            for (int j4 = 0; j4 < 24; j4++) {
                float4 r4 = *(const float4*)(rp + j4 * 4);
                a = fmaf(r4.x, tp[(j4 * 4 + 0) * 3], a);
                a = fmaf(r4.y, tp[(j4 * 4 + 1) * 3], a);
                a = fmaf(r4.z, tp[(j4 * 4 + 2) * 3], a);
                a = fmaf(r4.w, tp[(j4 * 4 + 3) * 3], a);
            }
            int e = e0 + el;
            if (e < E)
                out[(size_t)e * 96 + (slab * 4 + oo) * 3 + m] = a;
        }

        cp_wait<0>();      // next h tile landed
        __syncthreads();   // everyone done reading tmps/rws before overwrite
        par ^= 1;
    }
}

// ---------------------------------------------------------------------------
extern "C" void kernel_launch(void* const* d_in, const int* in_sizes, int n_in,
                              void* d_out, int out_size)
{
    const float* edges = (const float*)d_in[0];
    const float* feats = (const float*)d_in[1];
    const float* basis = (const float*)d_in[2];
    const float* W1    = (const float*)d_in[3];
    const float* b1    = (const float*)d_in[4];
    const float* g1    = (const float*)d_in[5];
    const float* beta1 = (const float*)d_in[6];
    const float* W2    = (const float*)d_in[7];
    const float* b2    = (const float*)d_in[8];
    const float* g2    = (const float*)d_in[9];
    const float* beta2 = (const float*)d_in[10];
    const float* W3    = (const float*)d_in[11];
    float* out = (float*)d_out;

    int E = in_sizes[0] / 32;
    if (E > E_MAX) E = E_MAX;

    mlp_tmp_kernel<<<(E + 7) / 8, 256>>>(edges, feats, basis,
                                         W1, b1, g1, beta1,
                                         W2, b2, g2, beta2, E);

    static bool attr_set = false;
    const int smem_bytes = SM2_FLOATS * (int)sizeof(float);  // 201,728
    if (!attr_set) {
        cudaFuncSetAttribute(fused_rw_kernel,
                             cudaFuncAttributeMaxDynamicSharedMemorySize, smem_bytes);
        attr_set = true;
    }
    dim3 grid(NE_CTAS, 8);   // 144 persistent CTAs: 18 edge-stripes x 8 slabs
    fused_rw_kernel<<<grid, K2_THREADS, smem_bytes>>>(W3, out, E);
}

// round 9
// speedup vs baseline: 1.3844x; 1.3844x over previous
#include <cuda_runtime.h>
#include <cuda_bf16.h>
#include <math.h>

#define E_MAX 32768
#define NSTRIPES 18

// ---------------- device scratch (allocation-free) -------------------------
// A images: per 32-edge tile, 32 rows x 256 B ([xh(64k)|xl(64k)] bf16, chunk-XOR swizzled)
__device__ unsigned g_aimg[(E_MAX / 32) * 2048];
// tmp fp32, m-major per edge: g_tmp[e*288 + m*96 + j]
__device__ float g_tmp[(size_t)E_MAX * 288];
// B images: per 384-col slab, 384 rows x 256 B ([wh|wl], swizzled)
__device__ unsigned char g_b[8 * 98304];

__device__ __forceinline__ float gelu_exact(float v) {
    return 0.5f * v * (1.0f + erff(v * 0.70710678118654752440f));
}
__device__ __forceinline__ unsigned smem_u32(const void* p) {
    return (unsigned)__cvta_generic_to_shared(p);
}
__device__ __forceinline__ void cp16(void* sdst, const void* gsrc) {
    asm volatile("cp.async.cg.shared.global [%0], [%1], 16;"
                 :: "r"(smem_u32(sdst)), "l"(gsrc));
}
__device__ __forceinline__ void cp_commit() { asm volatile("cp.async.commit_group;"); }
template <int N> __device__ __forceinline__ void cp_wait() {
    asm volatile("cp.async.wait_group %0;" :: "n"(N));
}

// ---- warp MMA primitives (baseline PTX: sm_80+, compiles for sm_103) ------
__device__ __forceinline__ void ldsm4(unsigned* r, unsigned addr) {
    asm volatile("ldmatrix.sync.aligned.m8n8.x4.shared.b16 {%0,%1,%2,%3}, [%4];"
        : "=r"(r[0]), "=r"(r[1]), "=r"(r[2]), "=r"(r[3]) : "r"(addr));
}
__device__ __forceinline__ void mma16816(float* d, const unsigned* a,
                                         const unsigned* b) {
    asm volatile("mma.sync.aligned.m16n8k16.row.col.f32.bf16.bf16.f32 "
        "{%0,%1,%2,%3}, {%4,%5,%6,%7}, {%8,%9}, {%0,%1,%2,%3};"
        : "+f"(d[0]), "+f"(d[1]), "+f"(d[2]), "+f"(d[3])
        : "r"(a[0]), "r"(a[1]), "r"(a[2]), "r"(a[3]), "r"(b[0]), "r"(b[1]));
}

// ---------------------------------------------------------------------------
// Kernel 1: MLP (Linear->LN->GELU)x2 -> bf16-split swizzled A image;
//           tmp = feats@basis -> fp32 m-major.
// ---------------------------------------------------------------------------
__global__ __launch_bounds__(256)
void mlp_tmp_kernel(const float* __restrict__ edges,
                    const float* __restrict__ feats,
                    const float* __restrict__ basis,
                    const float* __restrict__ W1, const float* __restrict__ b1,
                    const float* __restrict__ g1, const float* __restrict__ beta1,
                    const float* __restrict__ W2, const float* __restrict__ b2,
                    const float* __restrict__ g2, const float* __restrict__ beta2,
                    int E)
{
    __shared__ float W1s[32 * 64];
    __shared__ float W2s[64 * 64];
    __shared__ float hst[8][64];
    int tid = threadIdx.x;
    for (int i = tid; i < 32 * 64; i += 256) W1s[i] = W1[i];
    for (int i = tid; i < 64 * 64; i += 256) W2s[i] = W2[i];
    __syncthreads();

    int warp = tid >> 5, lane = tid & 31;
    int e = blockIdx.x * 8 + warp;
    if (e >= E) return;
    const unsigned FULL = 0xffffffffu;

    float xv = edges[(size_t)e * 32 + lane];
    float t0 = b1[lane], t1 = b1[lane + 32];
    #pragma unroll
    for (int k = 0; k < 32; k++) {
        float xk = __shfl_sync(FULL, xv, k);
        t0 = fmaf(xk, W1s[k * 64 + lane], t0);
        t1 = fmaf(xk, W1s[k * 64 + lane + 32], t1);
    }
    float s = t0 + t1, sq = t0 * t0 + t1 * t1;
    #pragma unroll
    for (int o = 16; o > 0; o >>= 1) {
        s += __shfl_xor_sync(FULL, s, o);
        sq += __shfl_xor_sync(FULL, sq, o);
    }
    float mean = s * (1.0f / 64.0f);
    float var = sq * (1.0f / 64.0f) - mean * mean;
    float rstd = rsqrtf(var + 1e-5f);
    float h0 = gelu_exact((t0 - mean) * rstd * g1[lane] + beta1[lane]);
    float h1 = gelu_exact((t1 - mean) * rstd * g1[lane + 32] + beta1[lane + 32]);

    t0 = b2[lane]; t1 = b2[lane + 32];
    #pragma unroll
    for (int k = 0; k < 32; k++) {
        float a = __shfl_sync(FULL, h0, k);
        float b = __shfl_sync(FULL, h1, k);
        t0 = fmaf(a, W2s[k * 64 + lane], t0);
        t0 = fmaf(b, W2s[(k + 32) * 64 + lane], t0);
        t1 = fmaf(a, W2s[k * 64 + lane + 32], t1);
        t1 = fmaf(b, W2s[(k + 32) * 64 + lane + 32], t1);
    }
    s = t0 + t1; sq = t0 * t0 + t1 * t1;
    #pragma unroll
    for (int o = 16; o > 0; o >>= 1) {
        s += __shfl_xor_sync(FULL, s, o);
        sq += __shfl_xor_sync(FULL, sq, o);
    }
    mean = s * (1.0f / 64.0f);
    var = sq * (1.0f / 64.0f) - mean * mean;
    rstd = rsqrtf(var + 1e-5f);
    float o0 = gelu_exact((t0 - mean) * rstd * g2[lane] + beta2[lane]);
    float o1 = gelu_exact((t1 - mean) * rstd * g2[lane + 32] + beta2[lane + 32]);

    // regroup to k-pairs, split hi/lo, write swizzled A image
    hst[warp][lane] = o0; hst[warp][lane + 32] = o1;
    __syncwarp();
    float va = hst[warp][2 * lane], vb = hst[warp][2 * lane + 1];
    __nv_bfloat16 ah = __float2bfloat16(va);
    __nv_bfloat16 al = __float2bfloat16(va - __bfloat162float(ah));
    __nv_bfloat16 bh = __float2bfloat16(vb);
    __nv_bfloat16 bl = __float2bfloat16(vb - __bfloat162float(bh));
    unsigned hp = ((unsigned)*(unsigned short*)&bh << 16) | *(unsigned short*)&ah;
    unsigned lp = ((unsigned)*(unsigned short*)&bl << 16) | *(unsigned short*)&al;
    {
        int row = e & 31;
        unsigned* img = g_aimg + (size_t)(e >> 5) * 2048 + row * 64;
        int ih = lane, il = 32 + lane;      // logical b32 indices (xh, xl)
        int ph = (((ih >> 2) ^ (row & 7)) << 2) | (ih & 3);
        int pl = (((il >> 2) ^ (row & 7)) << 2) | (il & 3);
        img[ph] = hp;
        img[pl] = lp;
    }

    // tmp[e][m*96 + i*3 + f] fp32
    const float* fp = feats + (size_t)e * 96 + lane * 3;
    float f0 = fp[0], f1 = fp[1], f2 = fp[2];
    const float* bp = basis + (size_t)e * 27;
    float* tr = g_tmp + (size_t)e * 288;
    #pragma unroll
    for (int f = 0; f < 3; f++)
        #pragma unroll
        for (int m = 0; m < 3; m++) {
            int q = f * 3 + m;
            tr[m * 96 + lane * 3 + f] = f0 * bp[q] + f1 * bp[9 + q] + f2 * bp[18 + q];
        }
}

// ---------------------------------------------------------------------------
// Prep: W3 bf16 split -> swizzled B images ([wh|wl] per 384-col slab)
// ---------------------------------------------------------------------------
__global__ __launch_bounds__(256)
void w3split_kernel(const float* __restrict__ W3)
{
    int idx = blockIdx.x * 256 + threadIdx.x;
    if (idx >= 3072 * 64) return;
    int n = idx >> 6, c = idx & 63;
    float w = W3[(size_t)c * 3072 + n];
    __nv_bfloat16 wh = __float2bfloat16(w);
    __nv_bfloat16 wl = __float2bfloat16(w - __bfloat162float(wh));
    int slab = n / 384, r = n - slab * 384;
    unsigned char* img = g_b + (size_t)slab * 98304 + r * 256;
    int bh = 2 * c, blo = 128 + 2 * c;
    int ph = (((bh >> 4) ^ (r & 7)) << 4) | (bh & 15);
    int pl = (((blo >> 4) ^ (r & 7)) << 4) | (blo & 15);
    *(unsigned short*)(img + ph) = *(unsigned short*)&wh;
    *(unsigned short*)(img + pl) = *(unsigned short*)&wl;
}

// ---------------------------------------------------------------------------
// Kernel 2: persistent warp-MMA GEMM + fused contraction.
// grid (18 stripes, 8 slabs), 384 threads = 12 warps.
// Warp tile: 16 edges x 64 cols; K=192 via 3-term split with A/B reuse.
// smem: B[98304] | A x2 [16384] | tmp[37376] | rw[49664]  = 201728 B
// ---------------------------------------------------------------------------
#define B_OFF   0
#define A_OFF   98304
#define TMP_OFF 114688
#define RW_OFF  152064
#define SMEM_SZ 201728
#define TMPS_STRIDE 292
#define RWS_STRIDE  388

__global__ __launch_bounds__(384, 1)
void hmma_rw_kernel(float* __restrict__ out, int E)
{
    extern __shared__ unsigned char sm[];
    const int tid = threadIdx.x;
    const int warp = tid >> 5, lane = tid & 31;
    const int slab = blockIdx.y;
    const int tiles = (E + 31) >> 5;

    float* tmps = (float*)(sm + TMP_OFF);
    float* rws  = (float*)(sm + RW_OFF);

    // GEMM warp mapping
    const int eg = warp & 1;              // 16-edge group
    const int n0 = (warp >> 1) * 64;      // col base (within 384)
    // ldmatrix lane address components
    const int arow = eg * 16 + (lane & 7) + ((lane >> 3) & 1) * 8;  // A row in tile
    const int akh  = (lane >> 4) & 1;                               // A k-half
    const int brow_base = n0 + ((lane >> 4) & 1) * 8 + (lane & 7);  // B row base
    const int bkh  = (lane >> 3) & 1;                               // B k-half
    // epilogue mapping: 384 = 3m x 32e x 4ch
    const int m  = tid % 3;
    const int p  = tid / 3;
    const int el = p & 31;
    const int oo = p >> 5;

    const unsigned sA0 = smem_u32(sm + A_OFF);
    const unsigned sB  = smem_u32(sm + B_OFF);

    // ---- prologue: B slab + A(t0), one cp.async group ----
    {
        const unsigned char* src = g_b + (size_t)slab * 98304;
        for (int q = tid; q < 6144; q += 384) cp16(sm + B_OFF + q * 16, src + q * 16);
        int t0 = blockIdx.x;
        if (t0 < tiles) {
            const unsigned* a = g_aimg + (size_t)t0 * 2048;
            for (int q = tid; q < 512; q += 384) cp16(sm + A_OFF + q * 16, a + q * 4);
        }
        cp_commit();
    }

    bool first = true;
    int par = 0;

    for (int tt = blockIdx.x; tt < tiles; tt += NSTRIPES) {
        if (first) { cp_wait<0>(); __syncthreads(); first = false; }

        // group T: tmp(tt)
        {
            const float* src = g_tmp + (size_t)tt * 32 * 288;
            for (int q = tid; q < 2304; q += 384) {
                int r = q / 72, c = q - r * 72;
                cp16(tmps + r * TMPS_STRIDE + c * 4, src + r * 288 + c * 4);
            }
            cp_commit();
        }
        // group H: A(tt + NSTRIPES) into other buffer
        {
            int tn = tt + NSTRIPES;
            if (tn < tiles) {
                const unsigned* a = g_aimg + (size_t)tn * 2048;
                unsigned char* dst = sm + A_OFF + (par ^ 1) * 8192;
                for (int q = tid; q < 512; q += 384) cp16(dst + q * 16, a + q * 4);
            }
            cp_commit();
        }

        // ---- GEMM: rw[32][384] = h_split[32][192] @ W_split[192][384] ----
        const unsigned sA = sA0 + par * 8192;
        float acc[8][4];
        #pragma unroll
        for (int i = 0; i < 8; i++)
            #pragma unroll
            for (int j = 0; j < 4; j++) acc[i][j] = 0.0f;

        #pragma unroll
        for (int ks = 0; ks < 4; ks++) {
            unsigned ahh[4], all[4];
            {
                int chunk = ks * 2 + akh;
                unsigned ad = sA + arow * 256 + ((chunk ^ (arow & 7)) << 4);
                ldsm4(ahh, ad);          // xh
                ldsm4(all, ad + 128);    // xl (XOR preserves bit3 -> +128 exact)
            }
            #pragma unroll
            for (int nf2 = 0; nf2 < 4; nf2++) {
                unsigned bw[4], bl[4];
                int brow = brow_base + nf2 * 16;
                int chunk = ks * 2 + bkh;
                unsigned bd = sB + brow * 256 + ((chunk ^ (brow & 7)) << 4);
                ldsm4(bw, bd);           // wh
                ldsm4(bl, bd + 128);     // wl
                #pragma unroll
                for (int hf = 0; hf < 2; hf++) {
                    int nf = nf2 * 2 + hf;
                    mma16816(acc[nf], ahh, bw + hf * 2);   // xh*wh
                    mma16816(acc[nf], all, bw + hf * 2);   // xl*wh
                    mma16816(acc[nf], ahh, bl + hf * 2);   // xh*wl
                }
            }
        }

        cp_wait<1>();   // tmp landed (A-next may still fly)

        // fragments -> rw smem
        {
            int r0 = eg * 16 + (lane >> 2);
            int c0 = n0 + (lane & 3) * 2;
            #pragma unroll
            for (int nf = 0; nf < 8; nf++) {
                float* w0 = rws + r0 * RWS_STRIDE + c0 + nf * 8;
                float* w1 = rws + (r0 + 8) * RWS_STRIDE + c0 + nf * 8;
                w0[0] = acc[nf][0]; w0[1] = acc[nf][1];
                w1[0] = acc[nf][2]; w1[1] = acc[nf][3];
            }
        }
        __syncthreads();

        // ---- contraction: out[e, ch, m] = sum_j rw[e][oo*96+j]*tmp[e][m*96+j]
        {
            const float* rp = rws  + el * RWS_STRIDE  + oo * 96;
            const float* tp = tmps + el * TMPS_STRIDE + m * 96;
            float a = 0.0f;
            #pragma unroll
            for (int j4 = 0; j4 < 24; j4++) {
                float4 r4 = *(const float4*)(rp + j4 * 4);
                float4 t4 = *(const float4*)(tp + j4 * 4);
                a = fmaf(r4.x, t4.x, a);
                a = fmaf(r4.y, t4.y, a);
                a = fmaf(r4.z, t4.z, a);
                a = fmaf(r4.w, t4.w, a);
            }
            int e = tt * 32 + el;
            if (e < E)
                out[(size_t)e * 96 + (slab * 4 + oo) * 3 + m] = a;
        }

        cp_wait<0>();     // next A landed
        __syncthreads();  // all reads of tmp/rw/A done before overwrite
        par ^= 1;
    }
}

// ---------------------------------------------------------------------------
extern "C" void kernel_launch(void* const* d_in, const int* in_sizes, int n_in,
                              void* d_out, int out_size)
{
    const float* edges = (const float*)d_in[0];
    const float* feats = (const float*)d_in[1];
    const float* basis = (const float*)d_in[2];
    const float* W1    = (const float*)d_in[3];
    const float* b1    = (const float*)d_in[4];
    const float* g1    = (const float*)d_in[5];
    const float* beta1 = (const float*)d_in[6];
    const float* W2    = (const float*)d_in[7];
    const float* b2    = (const float*)d_in[8];
    const float* g2    = (const float*)d_in[9];
    const float* beta2 = (const float*)d_in[10];
    const float* W3    = (const float*)d_in[11];
    float* out = (float*)d_out;

    int E = in_sizes[0] / 32;
    if (E > E_MAX) E = E_MAX;

    w3split_kernel<<<768, 256>>>(W3);
    mlp_tmp_kernel<<<(E + 7) / 8, 256>>>(edges, feats, basis,
                                         W1, b1, g1, beta1,
                                         W2, b2, g2, beta2, E);

    static bool attr_set = false;
    if (!attr_set) {
        cudaFuncSetAttribute(hmma_rw_kernel,
                             cudaFuncAttributeMaxDynamicSharedMemorySize, SMEM_SZ);
        attr_set = true;
    }
    dim3 grid(NSTRIPES, 8);
    hmma_rw_kernel<<<grid, 384, SMEM_SZ>>>(out, E);
}

// round 11
// speedup vs baseline: 1.8219x; 1.3160x over previous
#include <cuda_runtime.h>
#include <cuda_bf16.h>
#include <math.h>

#define E_MAX 32768
#define NSTRIPES 18

// ---------------- device scratch (allocation-free) -------------------------
// A images: per 32-edge tile, 32 rows x 256 B ([xh(64k)|xl(64k)] bf16, chunk-XOR swizzled)
__device__ unsigned g_aimg[(E_MAX / 32) * 2048];
// tmp fp32, m-major per edge: g_tmp[e*288 + m*96 + j]
__device__ float g_tmp[(size_t)E_MAX * 288];
// B images: per 384-col slab, 384 rows x 256 B ([wh|wl], swizzled)
__device__ unsigned char g_b[8 * 98304];

__device__ __forceinline__ float gelu_exact(float v) {
    return 0.5f * v * (1.0f + erff(v * 0.70710678118654752440f));
}
__device__ __forceinline__ unsigned smem_u32(const void* p) {
    return (unsigned)__cvta_generic_to_shared(p);
}
__device__ __forceinline__ void cp16(void* sdst, const void* gsrc) {
    asm volatile("cp.async.cg.shared.global [%0], [%1], 16;"
                 :: "r"(smem_u32(sdst)), "l"(gsrc));
}
__device__ __forceinline__ void cp_commit() { asm volatile("cp.async.commit_group;"); }
template <int N> __device__ __forceinline__ void cp_wait() {
    asm volatile("cp.async.wait_group %0;" :: "n"(N));
}

// ---- warp MMA primitives (baseline PTX: sm_80+, compiles for sm_103) ------
__device__ __forceinline__ void ldsm4(unsigned* r, unsigned addr) {
    asm volatile("ldmatrix.sync.aligned.m8n8.x4.shared.b16 {%0,%1,%2,%3}, [%4];"
        : "=r"(r[0]), "=r"(r[1]), "=r"(r[2]), "=r"(r[3]) : "r"(addr));
}
__device__ __forceinline__ void mma16816(float* d, const unsigned* a,
                                         const unsigned* b) {
    asm volatile("mma.sync.aligned.m16n8k16.row.col.f32.bf16.bf16.f32 "
        "{%0,%1,%2,%3}, {%4,%5,%6,%7}, {%8,%9}, {%0,%1,%2,%3};"
        : "+f"(d[0]), "+f"(d[1]), "+f"(d[2]), "+f"(d[3])
        : "r"(a[0]), "r"(a[1]), "r"(a[2]), "r"(a[3]), "r"(b[0]), "r"(b[1]));
}

// ---------------------------------------------------------------------------
// Kernel 1: MLP (Linear->LN->GELU)x2 -> bf16-split swizzled A image;
//           tmp = feats@basis -> fp32 m-major.
// ---------------------------------------------------------------------------
__global__ __launch_bounds__(256)
void mlp_tmp_kernel(const float* __restrict__ edges,
                    const float* __restrict__ feats,
                    const float* __restrict__ basis,
                    const float* __restrict__ W1, const float* __restrict__ b1,
                    const float* __restrict__ g1, const float* __restrict__ beta1,
                    const float* __restrict__ W2, const float* __restrict__ b2,
                    const float* __restrict__ g2, const float* __restrict__ beta2,
                    int E)
{
    __shared__ float W1s[32 * 64];
    __shared__ float W2s[64 * 64];
    __shared__ float hst[8][64];
    int tid = threadIdx.x;
    for (int i = tid; i < 32 * 64; i += 256) W1s[i] = W1[i];
    for (int i = tid; i < 64 * 64; i += 256) W2s[i] = W2[i];
    __syncthreads();

    int warp = tid >> 5, lane = tid & 31;
    int e = blockIdx.x * 8 + warp;
    if (e >= E) return;
    const unsigned FULL = 0xffffffffu;

    float xv = edges[(size_t)e * 32 + lane];
    float t0 = b1[lane], t1 = b1[lane + 32];
    #pragma unroll
    for (int k = 0; k < 32; k++) {
        float xk = __shfl_sync(FULL, xv, k);
        t0 = fmaf(xk, W1s[k * 64 + lane], t0);
        t1 = fmaf(xk, W1s[k * 64 + lane + 32], t1);
    }
    float s = t0 + t1, sq = t0 * t0 + t1 * t1;
    #pragma unroll
    for (int o = 16; o > 0; o >>= 1) {
        s += __shfl_xor_sync(FULL, s, o);
        sq += __shfl_xor_sync(FULL, sq, o);
    }
    float mean = s * (1.0f / 64.0f);
    float var = sq * (1.0f / 64.0f) - mean * mean;
    float rstd = rsqrtf(var + 1e-5f);
    float h0 = gelu_exact((t0 - mean) * rstd * g1[lane] + beta1[lane]);
    float h1 = gelu_exact((t1 - mean) * rstd * g1[lane + 32] + beta1[lane + 32]);

    t0 = b2[lane]; t1 = b2[lane + 32];
    #pragma unroll
    for (int k = 0; k < 32; k++) {
        float a = __shfl_sync(FULL, h0, k);
        float b = __shfl_sync(FULL, h1, k);
        t0 = fmaf(a, W2s[k * 64 + lane], t0);
        t0 = fmaf(b, W2s[(k + 32) * 64 + lane], t0);
        t1 = fmaf(a, W2s[k * 64 + lane + 32], t1);
        t1 = fmaf(b, W2s[(k + 32) * 64 + lane + 32], t1);
    }
    s = t0 + t1; sq = t0 * t0 + t1 * t1;
    #pragma unroll
    for (int o = 16; o > 0; o >>= 1) {
        s += __shfl_xor_sync(FULL, s, o);
        sq += __shfl_xor_sync(FULL, sq, o);
    }
    mean = s * (1.0f / 64.0f);
    var = sq * (1.0f / 64.0f) - mean * mean;
    rstd = rsqrtf(var + 1e-5f);
    float o0 = gelu_exact((t0 - mean) * rstd * g2[lane] + beta2[lane]);
    float o1 = gelu_exact((t1 - mean) * rstd * g2[lane + 32] + beta2[lane + 32]);

    // regroup to k-pairs, split hi/lo, write swizzled A image
    hst[warp][lane] = o0; hst[warp][lane + 32] = o1;
    __syncwarp();
    float va = hst[warp][2 * lane], vb = hst[warp][2 * lane + 1];
    __nv_bfloat16 ah = __float2bfloat16(va);
    __nv_bfloat16 al = __float2bfloat16(va - __bfloat162float(ah));
    __nv_bfloat16 bh = __float2bfloat16(vb);
    __nv_bfloat16 bl = __float2bfloat16(vb - __bfloat162float(bh));
    unsigned hp = ((unsigned)*(unsigned short*)&bh << 16) | *(unsigned short*)&ah;
    unsigned lp = ((unsigned)*(unsigned short*)&bl << 16) | *(unsigned short*)&al;
    {
        int row = e & 31;
        unsigned* img = g_aimg + (size_t)(e >> 5) * 2048 + row * 64;
        int ih = lane, il = 32 + lane;      // logical b32 indices (xh, xl)
        int ph = (((ih >> 2) ^ (row & 7)) << 2) | (ih & 3);
        int pl = (((il >> 2) ^ (row & 7)) << 2) | (il & 3);
        img[ph] = hp;
        img[pl] = lp;
    }

    // tmp[e][m*96 + i*3 + f] fp32
    const float* fp = feats + (size_t)e * 96 + lane * 3;
    float f0 = fp[0], f1 = fp[1], f2 = fp[2];
    const float* bp = basis + (size_t)e * 27;
    float* tr = g_tmp + (size_t)e * 288;
    #pragma unroll
    for (int f = 0; f < 3; f++)
        #pragma unroll
        for (int m = 0; m < 3; m++) {
            int q = f * 3 + m;
            tr[m * 96 + lane * 3 + f] = f0 * bp[q] + f1 * bp[9 + q] + f2 * bp[18 + q];
        }
}

// ---------------------------------------------------------------------------
// Prep: W3 bf16 split -> swizzled B images ([wh|wl] per 384-col slab)
// ---------------------------------------------------------------------------
__global__ __launch_bounds__(256)
void w3split_kernel(const float* __restrict__ W3)
{
    int idx = blockIdx.x * 256 + threadIdx.x;
    if (idx >= 3072 * 64) return;
    int n = idx >> 6, c = idx & 63;
    float w = W3[(size_t)c * 3072 + n];
    __nv_bfloat16 wh = __float2bfloat16(w);
    __nv_bfloat16 wl = __float2bfloat16(w - __bfloat162float(wh));
    int slab = n / 384, r = n - slab * 384;
    unsigned char* img = g_b + (size_t)slab * 98304 + r * 256;
    int bh = 2 * c, blo = 128 + 2 * c;
    int ph = (((bh >> 4) ^ (r & 7)) << 4) | (bh & 15);
    int pl = (((blo >> 4) ^ (r & 7)) << 4) | (blo & 15);
    *(unsigned short*)(img + ph) = *(unsigned short*)&wh;
    *(unsigned short*)(img + pl) = *(unsigned short*)&wl;
}

// ---------------------------------------------------------------------------
// Kernel 2: persistent warp-MMA GEMM with DIRECT fragment contraction.
// grid (18 stripes, 8 slabs), 384 threads = 12 warps.
// Warp tile: 32 edges x 32 cols (warp's cols lie inside ONE output channel:
// ch = warp/3, j-slice jb = (warp%3)*32). No rw smem round-trip.
// smem: B[98304] | A x2 [16384] | tmp[37376] | part[4608] = 156672 B
// ---------------------------------------------------------------------------
#define B_OFF    0
#define A_OFF    98304
#define TMP_OFF  114688
#define PART_OFF 152064
#define SMEM_SZ  156672
#define TMPS_STRIDE 292

__global__ __launch_bounds__(384, 1)
void hmma_rw_kernel(float* __restrict__ out, int E)
{
    extern __shared__ unsigned char sm[];
    const int tid = threadIdx.x;
    const int warp = tid >> 5, lane = tid & 31;
    const int slab = blockIdx.y;
    const int tiles = (E + 31) >> 5;
    const unsigned FULL = 0xffffffffu;

    float* tmps = (float*)(sm + TMP_OFF);
    float* part = (float*)(sm + PART_OFF);

    // GEMM warp mapping: 32 edges x 32 cols per warp
    const int n0 = warp * 32;             // col base (within 384)
    const int jb = (warp % 3) * 32;       // j-slice base within channel
    // ldmatrix lane address components (validated in R9)
    const int ar  = (lane & 7) + ((lane >> 3) & 1) * 8;   // + mt*16 = A row
    const int akh = (lane >> 4) & 1;                       // A k-half
    const int brow0 = n0 + ((lane >> 4) & 1) * 8 + (lane & 7);
    const int bkh = (lane >> 3) & 1;
    // fragment (row, col) mapping for contraction
    const int r0 = lane >> 2;             // + mt*16 (+8 for d2/d3)
    const int c0 = (lane & 3) * 2;        // + nf*8 within warp's 32 cols
    // final-output mapping: 384 = 3m x 32e x 4ch
    const int fm = tid % 3;
    const int fe = (tid / 3) & 31;
    const int fc = tid / 96;

    const unsigned sA0 = smem_u32(sm + A_OFF);
    const unsigned sB  = smem_u32(sm + B_OFF);

    // ---- prologue: B slab + A(t0), one cp.async group ----
    {
        const unsigned char* src = g_b + (size_t)slab * 98304;
        for (int q = tid; q < 6144; q += 384) cp16(sm + B_OFF + q * 16, src + q * 16);
        int t0 = blockIdx.x;
        if (t0 < tiles) {
            const unsigned* a = g_aimg + (size_t)t0 * 2048;
            for (int q = tid; q < 512; q += 384) cp16(sm + A_OFF + q * 16, a + q * 4);
        }
        cp_commit();
    }

    bool first = true;
    int par = 0;

    for (int tt = blockIdx.x; tt < tiles; tt += NSTRIPES) {
        if (first) { cp_wait<0>(); __syncthreads(); first = false; }

        // group T: tmp(tt)
        {
            const float* src = g_tmp + (size_t)tt * 32 * 288;
            for (int q = tid; q < 2304; q += 384) {
                int r = q / 72, c = q - r * 72;
                cp16(tmps + r * TMPS_STRIDE + c * 4, src + r * 288 + c * 4);
            }
            cp_commit();
        }
        // group H: A(tt + NSTRIPES) into other buffer
        {
            int tn = tt + NSTRIPES;
            if (tn < tiles) {
                const unsigned* a = g_aimg + (size_t)tn * 2048;
                unsigned char* dst = sm + A_OFF + (par ^ 1) * 8192;
                for (int q = tid; q < 512; q += 384) cp16(dst + q * 16, a + q * 4);
            }
            cp_commit();
        }

        // ---- GEMM: warp computes rw[32e][32c] in registers ----
        const unsigned sA = sA0 + par * 8192;
        float acc[2][4][4];
        #pragma unroll
        for (int mt = 0; mt < 2; mt++)
            #pragma unroll
            for (int nf = 0; nf < 4; nf++)
                #pragma unroll
                for (int j = 0; j < 4; j++) acc[mt][nf][j] = 0.0f;

        #pragma unroll
        for (int ks = 0; ks < 4; ks++) {
            unsigned ah[2][4], al[2][4];
            {
                int chunk = ks * 2 + akh;
                #pragma unroll
                for (int mt = 0; mt < 2; mt++) {
                    int row = mt * 16 + ar;
                    unsigned ad = sA + row * 256 + ((chunk ^ (row & 7)) << 4);
                    ldsm4(ah[mt], ad);         // xh
                    ldsm4(al[mt], ad + 128);   // xl
                }
            }
            unsigned bw[2][4], bl[2][4];
            {
                int chunk = ks * 2 + bkh;
                #pragma unroll
                for (int nf2 = 0; nf2 < 2; nf2++) {
                    int brow = brow0 + nf2 * 16;
                    unsigned bd = sB + brow * 256 + ((chunk ^ (brow & 7)) << 4);
                    ldsm4(bw[nf2], bd);        // wh
                    ldsm4(bl[nf2], bd + 128);  // wl
                }
            }
            #pragma unroll
            for (int mt = 0; mt < 2; mt++)
                #pragma unroll
                for (int nf2 = 0; nf2 < 2; nf2++)
                    #pragma unroll
                    for (int hf = 0; hf < 2; hf++) {
                        int nf = nf2 * 2 + hf;
                        mma16816(acc[mt][nf], ah[mt], bw[nf2] + hf * 2);  // xh*wh
                        mma16816(acc[mt][nf], al[mt], bw[nf2] + hf * 2);  // xl*wh
                        mma16816(acc[mt][nf], ah[mt], bl[nf2] + hf * 2);  // xh*wl
                    }
        }

        cp_wait<1>();      // tmp landed (A-next may still fly)
        __syncthreads();   // all tmp cp.async writes visible

        // ---- direct contraction from fragments ----
        // p[idx][m], idx = mt*2 + rowhalf  (rows: mt*16 + rh*8 + r0)
        float p[4][3];
        #pragma unroll
        for (int i = 0; i < 4; i++)
            #pragma unroll
            for (int m = 0; m < 3; m++) p[i][m] = 0.0f;

        #pragma unroll
        for (int mt = 0; mt < 2; mt++)
            #pragma unroll
            for (int rh = 0; rh < 2; rh++) {
                int row = mt * 16 + rh * 8 + r0;
                const float* trow = tmps + row * TMPS_STRIDE;
                int idx = mt * 2 + rh;
                #pragma unroll
                for (int nf = 0; nf < 4; nf++) {
                    float vx = acc[mt][nf][rh * 2 + 0];
                    float vy = acc[mt][nf][rh * 2 + 1];
                    int j = jb + nf * 8 + c0;
                    #pragma unroll
                    for (int m = 0; m < 3; m++) {
                        float2 t2 = *(const float2*)(trow + m * 96 + j);
                        p[idx][m] = fmaf(vx, t2.x, p[idx][m]);
                        p[idx][m] = fmaf(vy, t2.y, p[idx][m]);
                    }
                }
            }

        // reduce partials over lane&3 (4 lanes hold different col-slices)
        #pragma unroll
        for (int i = 0; i < 4; i++)
            #pragma unroll
            for (int m = 0; m < 3; m++) {
                p[i][m] += __shfl_xor_sync(FULL, p[i][m], 1);
                p[i][m] += __shfl_xor_sync(FULL, p[i][m], 2);
            }
        if ((lane & 3) == 0) {
            #pragma unroll
            for (int mt = 0; mt < 2; mt++)
                #pragma unroll
                for (int rh = 0; rh < 2; rh++) {
                    int row = mt * 16 + rh * 8 + r0;
                    int idx = mt * 2 + rh;
                    #pragma unroll
                    for (int m = 0; m < 3; m++)
                        part[warp * 96 + row * 3 + m] = p[idx][m];
                }
        }
        __syncthreads();

        // ---- final reduce over 3 j-slices + store ----
        {
            int base = fe * 3 + fm;
            float v = part[(fc * 3 + 0) * 96 + base]
                    + part[(fc * 3 + 1) * 96 + base]
                    + part[(fc * 3 + 2) * 96 + base];
            int e = tt * 32 + fe;
            if (e < E)
                out[(size_t)e * 96 + (slab * 4 + fc) * 3 + fm] = v;
        }

        cp_wait<0>();     // next A landed
        __syncthreads();  // part/tmp/A reads done before overwrite
        par ^= 1;
    }
}

// ---------------------------------------------------------------------------
extern "C" void kernel_launch(void* const* d_in, const int* in_sizes, int n_in,
                              void* d_out, int out_size)
{
    const float* edges = (const float*)d_in[0];
    const float* feats = (const float*)d_in[1];
    const float* basis = (const float*)d_in[2];
    const float* W1    = (const float*)d_in[3];
    const float* b1    = (const float*)d_in[4];
    const float* g1    = (const float*)d_in[5];
    const float* beta1 = (const float*)d_in[6];
    const float* W2    = (const float*)d_in[7];
    const float* b2    = (const float*)d_in[8];
    const float* g2    = (const float*)d_in[9];
    const float* beta2 = (const float*)d_in[10];
    const float* W3    = (const float*)d_in[11];
    float* out = (float*)d_out;

    int E = in_sizes[0] / 32;
    if (E > E_MAX) E = E_MAX;

    w3split_kernel<<<768, 256>>>(W3);
    mlp_tmp_kernel<<<(E + 7) / 8, 256>>>(edges, feats, basis,
                                         W1, b1, g1, beta1,
                                         W2, b2, g2, beta2, E);

    static bool attr_set = false;
    if (!attr_set) {
        cudaFuncSetAttribute(hmma_rw_kernel,
                             cudaFuncAttributeMaxDynamicSharedMemorySize, SMEM_SZ);
        attr_set = true;
    }
    dim3 grid(NSTRIPES, 8);
    hmma_rw_kernel<<<grid, 384, SMEM_SZ>>>(out, E);
}

// round 12
// speedup vs baseline: 1.8663x; 1.0244x over previous
#include <cuda_runtime.h>
#include <cuda_bf16.h>
#include <math.h>

#define E_MAX 32768
#define NSTRIPES 18

// ---------------- device scratch (allocation-free) -------------------------
// A images: per 32-edge tile, 32 rows x 256 B ([xh(64k)|xl(64k)] bf16, chunk-XOR swizzled)
__device__ unsigned g_aimg[(E_MAX / 32) * 2048];
// tmp fp32, m-major per edge: g_tmp[e*288 + m*96 + j]
__device__ float g_tmp[(size_t)E_MAX * 288];
// B images: per 384-col slab, 384 rows x 256 B ([wh|wl], swizzled)
__device__ unsigned char g_b[8 * 98304];

__device__ __forceinline__ float gelu_exact(float v) {
    return 0.5f * v * (1.0f + erff(v * 0.70710678118654752440f));
}
__device__ __forceinline__ unsigned smem_u32(const void* p) {
    return (unsigned)__cvta_generic_to_shared(p);
}
__device__ __forceinline__ void cp16(void* sdst, const void* gsrc) {
    asm volatile("cp.async.cg.shared.global [%0], [%1], 16;"
                 :: "r"(smem_u32(sdst)), "l"(gsrc));
}
__device__ __forceinline__ void cp_commit() { asm volatile("cp.async.commit_group;"); }
template <int N> __device__ __forceinline__ void cp_wait() {
    asm volatile("cp.async.wait_group %0;" :: "n"(N));
}

// ---- warp MMA primitives (baseline PTX: sm_80+, compiles for sm_103) ------
__device__ __forceinline__ void ldsm4(unsigned* r, unsigned addr) {
    asm volatile("ldmatrix.sync.aligned.m8n8.x4.shared.b16 {%0,%1,%2,%3}, [%4];"
        : "=r"(r[0]), "=r"(r[1]), "=r"(r[2]), "=r"(r[3]) : "r"(addr));
}
__device__ __forceinline__ void mma16816(float* d, const unsigned* a,
                                         const unsigned* b) {
    asm volatile("mma.sync.aligned.m16n8k16.row.col.f32.bf16.bf16.f32 "
        "{%0,%1,%2,%3}, {%4,%5,%6,%7}, {%8,%9}, {%0,%1,%2,%3};"
        : "+f"(d[0]), "+f"(d[1]), "+f"(d[2]), "+f"(d[3])
        : "r"(a[0]), "r"(a[1]), "r"(a[2]), "r"(a[3]), "r"(b[0]), "r"(b[1]));
}

// ---------------------------------------------------------------------------
// Kernel 1: MLP (Linear->LN->GELU)x2 -> bf16-split swizzled A image;
//           tmp = feats@basis -> fp32 m-major.
// ---------------------------------------------------------------------------
__global__ __launch_bounds__(256)
void mlp_tmp_kernel(const float* __restrict__ edges,
                    const float* __restrict__ feats,
                    const float* __restrict__ basis,
                    const float* __restrict__ W1, const float* __restrict__ b1,
                    const float* __restrict__ g1, const float* __restrict__ beta1,
                    const float* __restrict__ W2, const float* __restrict__ b2,
                    const float* __restrict__ g2, const float* __restrict__ beta2,
                    int E)
{
    __shared__ float W1s[32 * 64];
    __shared__ float W2s[64 * 64];
    __shared__ float hst[8][64];
    int tid = threadIdx.x;
    for (int i = tid; i < 32 * 64; i += 256) W1s[i] = W1[i];
    for (int i = tid; i < 64 * 64; i += 256) W2s[i] = W2[i];
    __syncthreads();

    int warp = tid >> 5, lane = tid & 31;
    int e = blockIdx.x * 8 + warp;
    if (e >= E) return;
    const unsigned FULL = 0xffffffffu;

    float xv = edges[(size_t)e * 32 + lane];
    float t0 = b1[lane], t1 = b1[lane + 32];
    #pragma unroll
    for (int k = 0; k < 32; k++) {
        float xk = __shfl_sync(FULL, xv, k);
        t0 = fmaf(xk, W1s[k * 64 + lane], t0);
        t1 = fmaf(xk, W1s[k * 64 + lane + 32], t1);
    }
    float s = t0 + t1, sq = t0 * t0 + t1 * t1;
    #pragma unroll
    for (int o = 16; o > 0; o >>= 1) {
        s += __shfl_xor_sync(FULL, s, o);
        sq += __shfl_xor_sync(FULL, sq, o);
    }
    float mean = s * (1.0f / 64.0f);
    float var = sq * (1.0f / 64.0f) - mean * mean;
    float rstd = rsqrtf(var + 1e-5f);
    float h0 = gelu_exact((t0 - mean) * rstd * g1[lane] + beta1[lane]);
    float h1 = gelu_exact((t1 - mean) * rstd * g1[lane + 32] + beta1[lane + 32]);

    t0 = b2[lane]; t1 = b2[lane + 32];
    #pragma unroll
    for (int k = 0; k < 32; k++) {
        float a = __shfl_sync(FULL, h0, k);
        float b = __shfl_sync(FULL, h1, k);
        t0 = fmaf(a, W2s[k * 64 + lane], t0);
        t0 = fmaf(b, W2s[(k + 32) * 64 + lane], t0);
        t1 = fmaf(a, W2s[k * 64 + lane + 32], t1);
        t1 = fmaf(b, W2s[(k + 32) * 64 + lane + 32], t1);
    }
    s = t0 + t1; sq = t0 * t0 + t1 * t1;
    #pragma unroll
    for (int o = 16; o > 0; o >>= 1) {
        s += __shfl_xor_sync(FULL, s, o);
        sq += __shfl_xor_sync(FULL, sq, o);
    }
    mean = s * (1.0f / 64.0f);
    var = sq * (1.0f / 64.0f) - mean * mean;
    rstd = rsqrtf(var + 1e-5f);
    float o0 = gelu_exact((t0 - mean) * rstd * g2[lane] + beta2[lane]);
    float o1 = gelu_exact((t1 - mean) * rstd * g2[lane + 32] + beta2[lane + 32]);

    // regroup to k-pairs, split hi/lo, write swizzled A image
    hst[warp][lane] = o0; hst[warp][lane + 32] = o1;
    __syncwarp();
    float va = hst[warp][2 * lane], vb = hst[warp][2 * lane + 1];
    __nv_bfloat16 ah = __float2bfloat16(va);
    __nv_bfloat16 al = __float2bfloat16(va - __bfloat162float(ah));
    __nv_bfloat16 bh = __float2bfloat16(vb);
    __nv_bfloat16 bl = __float2bfloat16(vb - __bfloat162float(bh));
    unsigned hp = ((unsigned)*(unsigned short*)&bh << 16) | *(unsigned short*)&ah;
    unsigned lp = ((unsigned)*(unsigned short*)&bl << 16) | *(unsigned short*)&al;
    {
        int row = e & 31;
        unsigned* img = g_aimg + (size_t)(e >> 5) * 2048 + row * 64;
        int ih = lane, il = 32 + lane;      // logical b32 indices (xh, xl)
        int ph = (((ih >> 2) ^ (row & 7)) << 2) | (ih & 3);
        int pl = (((il >> 2) ^ (row & 7)) << 2) | (il & 3);
        img[ph] = hp;
        img[pl] = lp;
    }

    // tmp[e][m*96 + i*3 + f] fp32
    const float* fp = feats + (size_t)e * 96 + lane * 3;
    float f0 = fp[0], f1 = fp[1], f2 = fp[2];
    const float* bp = basis + (size_t)e * 27;
    float* tr = g_tmp + (size_t)e * 288;
    #pragma unroll
    for (int f = 0; f < 3; f++)
        #pragma unroll
        for (int m = 0; m < 3; m++) {
            int q = f * 3 + m;
            tr[m * 96 + lane * 3 + f] = f0 * bp[q] + f1 * bp[9 + q] + f2 * bp[18 + q];
        }
}

// ---------------------------------------------------------------------------
// Prep: W3 bf16 split -> swizzled B images ([wh|wl] per 384-col slab)
// ---------------------------------------------------------------------------
__global__ __launch_bounds__(256)
void w3split_kernel(const float* __restrict__ W3)
{
    int idx = blockIdx.x * 256 + threadIdx.x;
    if (idx >= 3072 * 64) return;
    int n = idx >> 6, c = idx & 63;
    float w = W3[(size_t)c * 3072 + n];
    __nv_bfloat16 wh = __float2bfloat16(w);
    __nv_bfloat16 wl = __float2bfloat16(w - __bfloat162float(wh));
    int slab = n / 384, r = n - slab * 384;
    unsigned char* img = g_b + (size_t)slab * 98304 + r * 256;
    int bh = 2 * c, blo = 128 + 2 * c;
    int ph = (((bh >> 4) ^ (r & 7)) << 4) | (bh & 15);
    int pl = (((blo >> 4) ^ (r & 7)) << 4) | (blo & 15);
    *(unsigned short*)(img + ph) = *(unsigned short*)&wh;
    *(unsigned short*)(img + pl) = *(unsigned short*)&wl;
}

// ---------------------------------------------------------------------------
// Kernel 2: persistent warp-MMA GEMM, B fragments HOISTED to registers,
// direct fragment contraction. grid (18 stripes, 8 slabs), 384 thr = 12 warps.
// Warp tile: 32 edges x 32 cols (ch = warp/3, jb = (warp%3)*32).
// smem: B[98304] | A x2 [16384] | tmp[37376] | part[4608] = 156672 B
// ---------------------------------------------------------------------------
#define B_OFF    0
#define A_OFF    98304
#define TMP_OFF  114688
#define PART_OFF 152064
#define SMEM_SZ  156672
#define TMPS_STRIDE 292

__global__ __launch_bounds__(384, 1)
void hmma_rw_kernel(float* __restrict__ out, int E)
{
    extern __shared__ unsigned char sm[];
    const int tid = threadIdx.x;
    const int warp = tid >> 5, lane = tid & 31;
    const int slab = blockIdx.y;
    const int tiles = (E + 31) >> 5;
    const unsigned FULL = 0xffffffffu;

    float* tmps = (float*)(sm + TMP_OFF);
    float* part = (float*)(sm + PART_OFF);

    // GEMM warp mapping: 32 edges x 32 cols per warp
    const int n0 = warp * 32;             // col base (within 384)
    const int jb = (warp % 3) * 32;       // j-slice base within channel
    // ldmatrix lane address components (validated in R9/R11)
    const int ar  = (lane & 7) + ((lane >> 3) & 1) * 8;   // + mt*16 = A row
    const int akh = (lane >> 4) & 1;                       // A k-half
    const int brow0 = n0 + ((lane >> 4) & 1) * 8 + (lane & 7);
    const int bkh = (lane >> 3) & 1;
    // fragment (row, col) mapping for contraction
    const int r0 = lane >> 2;             // + mt*16 (+8 for d2/d3)
    const int c0 = (lane & 3) * 2;        // + nf*8 within warp's 32 cols
    // final-output mapping: 384 = 3m x 32e x 4ch
    const int fm = tid % 3;
    const int fe = (tid / 3) & 31;
    const int fc = tid / 96;

    const unsigned sA0 = smem_u32(sm + A_OFF);
    const unsigned sB  = smem_u32(sm + B_OFF);

    // ---- prologue: B slab + A(t0), one cp.async group ----
    {
        const unsigned char* src = g_b + (size_t)slab * 98304;
        for (int q = tid; q < 6144; q += 384) cp16(sm + B_OFF + q * 16, src + q * 16);
        int t0 = blockIdx.x;
        if (t0 < tiles) {
            const unsigned* a = g_aimg + (size_t)t0 * 2048;
            for (int q = tid; q < 512; q += 384) cp16(sm + A_OFF + q * 16, a + q * 4);
        }
        cp_commit();
    }
    cp_wait<0>();
    __syncthreads();

    // ---- hoist: load ALL B fragments once (B slab is tile-invariant) ----
    // bw[ks][nf2], bl[ks][nf2] : 4 ks x 2 nf2 x 4 regs x 2 = 64 regs
    unsigned bw[4][2][4], bl[4][2][4];
    #pragma unroll
    for (int ks = 0; ks < 4; ks++) {
        int chunk = ks * 2 + bkh;
        #pragma unroll
        for (int nf2 = 0; nf2 < 2; nf2++) {
            int brow = brow0 + nf2 * 16;
            unsigned bd = sB + brow * 256 + ((chunk ^ (brow & 7)) << 4);
            ldsm4(bw[ks][nf2], bd);        // wh
            ldsm4(bl[ks][nf2], bd + 128);  // wl
        }
    }

    int par = 0;

    for (int tt = blockIdx.x; tt < tiles; tt += NSTRIPES) {
        // group T: tmp(tt)
        {
            const float* src = g_tmp + (size_t)tt * 32 * 288;
            for (int q = tid; q < 2304; q += 384) {
                int r = q / 72, c = q - r * 72;
                cp16(tmps + r * TMPS_STRIDE + c * 4, src + r * 288 + c * 4);
            }
            cp_commit();
        }
        // group H: A(tt + NSTRIPES) into other buffer
        {
            int tn = tt + NSTRIPES;
            if (tn < tiles) {
                const unsigned* a = g_aimg + (size_t)tn * 2048;
                unsigned char* dst = sm + A_OFF + (par ^ 1) * 8192;
                for (int q = tid; q < 512; q += 384) cp16(dst + q * 16, a + q * 4);
            }
            cp_commit();
        }

        // ---- GEMM: warp computes rw[32e][32c] in registers ----
        const unsigned sA = sA0 + par * 8192;
        float acc[2][4][4];
        #pragma unroll
        for (int mt = 0; mt < 2; mt++)
            #pragma unroll
            for (int nf = 0; nf < 4; nf++)
                #pragma unroll
                for (int j = 0; j < 4; j++) acc[mt][nf][j] = 0.0f;

        #pragma unroll
        for (int ks = 0; ks < 4; ks++) {
            unsigned ah[2][4], al[2][4];
            int chunk = ks * 2 + akh;
            #pragma unroll
            for (int mt = 0; mt < 2; mt++) {
                int row = mt * 16 + ar;
                unsigned ad = sA + row * 256 + ((chunk ^ (row & 7)) << 4);
                ldsm4(ah[mt], ad);         // xh
                ldsm4(al[mt], ad + 128);   // xl
            }
            #pragma unroll
            for (int mt = 0; mt < 2; mt++)
                #pragma unroll
                for (int nf2 = 0; nf2 < 2; nf2++)
                    #pragma unroll
                    for (int hf = 0; hf < 2; hf++) {
                        int nf = nf2 * 2 + hf;
                        mma16816(acc[mt][nf], ah[mt], bw[ks][nf2] + hf * 2); // xh*wh
                        mma16816(acc[mt][nf], al[mt], bw[ks][nf2] + hf * 2); // xl*wh
                        mma16816(acc[mt][nf], ah[mt], bl[ks][nf2] + hf * 2); // xh*wl
                    }
        }

        cp_wait<1>();      // tmp landed (A-next may still fly)
        __syncthreads();   // all tmp cp.async writes visible

        // ---- direct contraction from fragments ----
        float p[4][3];
        #pragma unroll
        for (int i = 0; i < 4; i++)
            #pragma unroll
            for (int m = 0; m < 3; m++) p[i][m] = 0.0f;

        #pragma unroll
        for (int mt = 0; mt < 2; mt++)
            #pragma unroll
            for (int rh = 0; rh < 2; rh++) {
                int row = mt * 16 + rh * 8 + r0;
                const float* trow = tmps + row * TMPS_STRIDE;
                int idx = mt * 2 + rh;
                #pragma unroll
                for (int nf = 0; nf < 4; nf++) {
                    float vx = acc[mt][nf][rh * 2 + 0];
                    float vy = acc[mt][nf][rh * 2 + 1];
                    int j = jb + nf * 8 + c0;
                    #pragma unroll
                    for (int m = 0; m < 3; m++) {
                        float2 t2 = *(const float2*)(trow + m * 96 + j);
                        p[idx][m] = fmaf(vx, t2.x, p[idx][m]);
                        p[idx][m] = fmaf(vy, t2.y, p[idx][m]);
                    }
                }
            }

        // reduce partials over lane&3 (4 lanes hold different col-slices)
        #pragma unroll
        for (int i = 0; i < 4; i++)
            #pragma unroll
            for (int m = 0; m < 3; m++) {
                p[i][m] += __shfl_xor_sync(FULL, p[i][m], 1);
                p[i][m] += __shfl_xor_sync(FULL, p[i][m], 2);
            }
        if ((lane & 3) == 0) {
            #pragma unroll
            for (int mt = 0; mt < 2; mt++)
                #pragma unroll
                for (int rh = 0; rh < 2; rh++) {
                    int row = mt * 16 + rh * 8 + r0;
                    int idx = mt * 2 + rh;
                    #pragma unroll
                    for (int m = 0; m < 3; m++)
                        part[warp * 96 + row * 3 + m] = p[idx][m];
                }
        }
        __syncthreads();

        // ---- final reduce over 3 j-slices + store ----
        {
            int base = fe * 3 + fm;
            float v = part[(fc * 3 + 0) * 96 + base]
                    + part[(fc * 3 + 1) * 96 + base]
                    + part[(fc * 3 + 2) * 96 + base];
            int e = tt * 32 + fe;
            if (e < E)
                out[(size_t)e * 96 + (slab * 4 + fc) * 3 + fm] = v;
        }

        cp_wait<0>();     // next A landed
        __syncthreads();  // part/tmp/A reads done before overwrite
        par ^= 1;
    }
}

// ---------------------------------------------------------------------------
extern "C" void kernel_launch(void* const* d_in, const int* in_sizes, int n_in,
                              void* d_out, int out_size)
{
    const float* edges = (const float*)d_in[0];
    const float* feats = (const float*)d_in[1];
    const float* basis = (const float*)d_in[2];
    const float* W1    = (const float*)d_in[3];
    const float* b1    = (const float*)d_in[4];
    const float* g1    = (const float*)d_in[5];
    const float* beta1 = (const float*)d_in[6];
    const float* W2    = (const float*)d_in[7];
    const float* b2    = (const float*)d_in[8];
    const float* g2    = (const float*)d_in[9];
    const float* beta2 = (const float*)d_in[10];
    const float* W3    = (const float*)d_in[11];
    float* out = (float*)d_out;

    int E = in_sizes[0] / 32;
    if (E > E_MAX) E = E_MAX;

    w3split_kernel<<<768, 256>>>(W3);
    mlp_tmp_kernel<<<(E + 7) / 8, 256>>>(edges, feats, basis,
                                         W1, b1, g1, beta1,
                                         W2, b2, g2, beta2, E);

    static bool attr_set = false;
    if (!attr_set) {
        cudaFuncSetAttribute(hmma_rw_kernel,
                             cudaFuncAttributeMaxDynamicSharedMemorySize, SMEM_SZ);
        attr_set = true;
    }
    dim3 grid(NSTRIPES, 8);
    hmma_rw_kernel<<<grid, 384, SMEM_SZ>>>(out, E);
}